// round 1
// baseline (speedup 1.0000x reference)
#include <cuda_runtime.h>
#include <cstdint>

// LinearInterpolator: out = lerp(y_points) at x_samp over sorted x_points.
// Inputs (metadata order): x_samp [256*32768] f32, x_points [16384] f32,
//                          y_points [16384] f32. Output f32, same shape as x_samp.
//
// Strategy:
//  1) build_lut_kernel: lut[j] = largest knot index i whose cell(x_points[i]) <= j,
//     over a uniform 16384-cell grid spanning [x_points[0], x_points[n-1]].
//     Because the cell map is monotone and computed with identical f32 ops in
//     both kernels, the true interval index for any sample in cell j is <= lut[j],
//     so the main kernel only ever scans DOWNWARD (expected <1 step).
//  2) interp_kernel: stages (x_i, y_i) float2 pairs (128KB) + uint16 LUT (32KB)
//     into shared memory; per sample: cell -> lut -> short down-scan -> lerp.

#define LUT_SIZE 16384
#define THREADS  1024

__device__ unsigned short g_lut[LUT_SIZE + 2];

__device__ __forceinline__ int cell_of(float v, float x_lo, float inv_w) {
    // Deterministic, monotone-in-v mapping; identical SASS in both kernels.
    return (int)__fmul_rn(__fsub_rn(v, x_lo), inv_w);
}

__global__ void build_lut_kernel(const float* __restrict__ xp, int n) {
    int j = blockIdx.x * blockDim.x + threadIdx.x;
    if (j > LUT_SIZE) return;
    float x_lo = __ldg(&xp[0]);
    float x_hi = __ldg(&xp[n - 1]);
    float inv_w = __fdiv_rn((float)LUT_SIZE, __fsub_rn(x_hi, x_lo));
    // Largest i with cell(xp[i]) <= j. i=0 always qualifies (cell=0, j>=0).
    int lo = 0, hi = n - 1;
    #pragma unroll 1
    while (lo < hi) {
        int mid = (lo + hi + 1) >> 1;
        if (cell_of(__ldg(&xp[mid]), x_lo, inv_w) <= j) lo = mid;
        else hi = mid - 1;
    }
    if (lo > n - 2) lo = n - 2;           // keep idx+1 in bounds downstream
    g_lut[j] = (unsigned short)lo;
}

__device__ __forceinline__ float interp1(float x, const float2* __restrict__ s_knots,
                                         const unsigned short* __restrict__ s_lut,
                                         float x_lo, float inv_w) {
    int j = cell_of(x, x_lo, inv_w);
    j = min(j, LUT_SIZE);
    int idx = (int)s_lut[j];
    float2 k0 = s_knots[idx];
    // Down-only scan: lut[j] >= true index by construction. Expected ~0.5 iters.
    while (k0.x > x) {
        --idx;
        k0 = s_knots[idx];
    }
    float2 k1 = s_knots[idx + 1];
    float t = __fdividef(__fsub_rn(x, k0.x), __fsub_rn(k1.x, k0.x));
    return fmaf(t, k1.y - k0.y, k0.y);
}

extern __shared__ unsigned char smem_raw[];

__global__ __launch_bounds__(THREADS, 1)
void interp_kernel(const float* __restrict__ xs, const float* __restrict__ xp,
                   const float* __restrict__ yp, float* __restrict__ out,
                   int total, int n) {
    float2* s_knots = reinterpret_cast<float2*>(smem_raw);
    unsigned short* s_lut =
        reinterpret_cast<unsigned short*>(smem_raw + (size_t)n * sizeof(float2));

    // Stage knot pairs and LUT into shared memory (coalesced).
    for (int i = threadIdx.x; i < n; i += blockDim.x)
        s_knots[i] = make_float2(__ldg(&xp[i]), __ldg(&yp[i]));
    for (int i = threadIdx.x; i <= LUT_SIZE; i += blockDim.x)
        s_lut[i] = g_lut[i];
    __syncthreads();

    float x_lo = s_knots[0].x;
    float x_hi = s_knots[n - 1].x;
    float inv_w = __fdiv_rn((float)LUT_SIZE, __fsub_rn(x_hi, x_lo));

    int tid = blockIdx.x * blockDim.x + threadIdx.x;
    int stride = gridDim.x * blockDim.x;
    int total4 = total >> 2;

    const float4* __restrict__ xs4 = reinterpret_cast<const float4*>(xs);
    float4* __restrict__ out4 = reinterpret_cast<float4*>(out);

    for (int t = tid; t < total4; t += stride) {
        float4 v = xs4[t];
        float4 r;
        r.x = interp1(v.x, s_knots, s_lut, x_lo, inv_w);
        r.y = interp1(v.y, s_knots, s_lut, x_lo, inv_w);
        r.z = interp1(v.z, s_knots, s_lut, x_lo, inv_w);
        r.w = interp1(v.w, s_knots, s_lut, x_lo, inv_w);
        out4[t] = r;
    }
    // Scalar tail (total not divisible by 4).
    for (int t = (total4 << 2) + tid; t < total; t += stride)
        out[t] = interp1(xs[t], s_knots, s_lut, x_lo, inv_w);
}

extern "C" void kernel_launch(void* const* d_in, const int* in_sizes, int n_in,
                              void* d_out, int out_size) {
    const float* xs = (const float*)d_in[0];
    const float* xp = (const float*)d_in[1];
    const float* yp = (const float*)d_in[2];
    float* out = (float*)d_out;
    int total = in_sizes[0];
    int n = in_sizes[1];

    build_lut_kernel<<<(LUT_SIZE + 256) / 256, 256>>>(xp, n);

    size_t smem_bytes = (size_t)n * sizeof(float2)
                      + (size_t)(LUT_SIZE + 2) * sizeof(unsigned short);
    cudaFuncSetAttribute(interp_kernel,
                         cudaFuncAttributeMaxDynamicSharedMemorySize,
                         (int)smem_bytes);

    int sm_count = 148, dev = 0;
    cudaGetDevice(&dev);
    cudaDeviceGetAttribute(&sm_count, cudaDevAttrMultiProcessorCount, dev);
    if (sm_count <= 0) sm_count = 148;

    interp_kernel<<<sm_count, THREADS, smem_bytes>>>(xs, xp, yp, out, total, n);
}

// round 2
// speedup vs baseline: 1.0597x; 1.0597x over previous
#include <cuda_runtime.h>
#include <cstdint>

// LinearInterpolator on GB300.
//  - build_lut_kernel: lut[j] = largest knot index i with cell(x_i) <= j over a
//    uniform 16384-cell grid. Identical f32 cell math in both kernels guarantees
//    the main kernel's correction scan is DOWN-only (expected <1 step).
//  - interp_kernel: SMEM holds s_x[16384] (f32, 64KB), s_ys[16384] ((y_i, slope_i)
//    float2, 128KB), and the u16 LUT (32KB). Per sample:
//    cell -> lut -> gather x[idx] (scan check) & ys[idx] in parallel -> one FMA.
//    ILP=8 per thread (2x float4) to cover the LDS latency chain.

#define LUT_SIZE 16384
#define THREADS  1024

__device__ unsigned short g_lut[LUT_SIZE + 2];

__device__ __forceinline__ int cell_of(float v, float x_lo, float inv_w) {
    // Deterministic monotone mapping; identical ops in build + main kernels.
    return (int)__fmul_rn(__fsub_rn(v, x_lo), inv_w);
}

__global__ void build_lut_kernel(const float* __restrict__ xp, int n) {
    int j = blockIdx.x * blockDim.x + threadIdx.x;
    if (j > LUT_SIZE) return;
    float x_lo = __ldg(&xp[0]);
    float x_hi = __ldg(&xp[n - 1]);
    float inv_w = __fdiv_rn((float)LUT_SIZE, __fsub_rn(x_hi, x_lo));
    int lo = 0, hi = n - 1;
    #pragma unroll 1
    while (lo < hi) {
        int mid = (lo + hi + 1) >> 1;
        if (cell_of(__ldg(&xp[mid]), x_lo, inv_w) <= j) lo = mid;
        else hi = mid - 1;
    }
    if (lo > n - 2) lo = n - 2;            // keep idx, idx+1 in bounds downstream
    g_lut[j] = (unsigned short)lo;
}

extern __shared__ unsigned char smem_raw[];

__device__ __forceinline__ float interp1(float x,
                                         const float* __restrict__ s_x,
                                         const float2* __restrict__ s_ys,
                                         const unsigned short* __restrict__ s_lut,
                                         float x_lo, float inv_w) {
    int j = cell_of(x, x_lo, inv_w);
    j = min(j, LUT_SIZE);
    int idx = (int)s_lut[j];
    float xi = s_x[idx];
    // Down-only correction: lut[j] >= true index by construction.
    while (xi > x) { xi = s_x[--idx]; }
    float2 ysv = s_ys[idx];                 // (y_i, slope_i)
    return fmaf(ysv.y, __fsub_rn(x, xi), ysv.x);
}

__global__ __launch_bounds__(THREADS, 1)
void interp_kernel(const float* __restrict__ xs, const float* __restrict__ xp,
                   const float* __restrict__ yp, float* __restrict__ out,
                   int total, int n) {
    float* s_x  = reinterpret_cast<float*>(smem_raw);                       // n f32
    float2* s_ys = reinterpret_cast<float2*>(smem_raw + (size_t)n * 4);     // n float2
    unsigned short* s_lut =
        reinterpret_cast<unsigned short*>(smem_raw + (size_t)n * 12);

    // Stage knots (compute slope on the fly) and LUT. Coalesced; data L2-hot.
    for (int i = threadIdx.x; i < n; i += blockDim.x) {
        float xi = xp[i];
        float yi = yp[i];
        s_x[i] = xi;
        float sl = 0.0f;
        if (i < n - 1) sl = __fdiv_rn(yp[i + 1] - yi, xp[i + 1] - xi);
        s_ys[i] = make_float2(yi, sl);
    }
    for (int i = threadIdx.x; i <= LUT_SIZE; i += blockDim.x)
        s_lut[i] = g_lut[i];
    __syncthreads();

    float x_lo = s_x[0];
    float x_hi = s_x[n - 1];
    float inv_w = __fdiv_rn((float)LUT_SIZE, __fsub_rn(x_hi, x_lo));

    int tid = blockIdx.x * blockDim.x + threadIdx.x;
    int stride = gridDim.x * blockDim.x;
    int T4 = total >> 2;

    const float4* __restrict__ xs4 = reinterpret_cast<const float4*>(xs);
    float4* __restrict__ out4 = reinterpret_cast<float4*>(out);

    // ILP = 8: two float4 loads per iteration, 8 independent interp chains.
    for (int t = tid; t < T4; t += 2 * stride) {
        int t2 = t + stride;
        bool hb = t2 < T4;
        float4 a = xs4[t];
        float4 b = hb ? xs4[t2] : a;

        float v[8] = {a.x, a.y, a.z, a.w, b.x, b.y, b.z, b.w};
        float r[8];
        #pragma unroll
        for (int k = 0; k < 8; k++)
            r[k] = interp1(v[k], s_x, s_ys, s_lut, x_lo, inv_w);

        out4[t] = make_float4(r[0], r[1], r[2], r[3]);
        if (hb) out4[t2] = make_float4(r[4], r[5], r[6], r[7]);
    }

    // Scalar tail (total not divisible by 4) — empty for this shape, kept for safety.
    for (int t = (T4 << 2) + tid; t < total; t += stride)
        out[t] = interp1(xs[t], s_x, s_ys, s_lut, x_lo, inv_w);
}

extern "C" void kernel_launch(void* const* d_in, const int* in_sizes, int n_in,
                              void* d_out, int out_size) {
    const float* xs = (const float*)d_in[0];
    const float* xp = (const float*)d_in[1];
    const float* yp = (const float*)d_in[2];
    float* out = (float*)d_out;
    int total = in_sizes[0];
    int n = in_sizes[1];

    build_lut_kernel<<<(LUT_SIZE + 256) / 256, 256>>>(xp, n);

    size_t smem_bytes = (size_t)n * 12 + (size_t)(LUT_SIZE + 2) * sizeof(unsigned short);
    cudaFuncSetAttribute(interp_kernel,
                         cudaFuncAttributeMaxDynamicSharedMemorySize,
                         (int)smem_bytes);

    int sm_count = 148, dev = 0;
    cudaGetDevice(&dev);
    cudaDeviceGetAttribute(&sm_count, cudaDevAttrMultiProcessorCount, dev);
    if (sm_count <= 0) sm_count = 148;

    interp_kernel<<<sm_count, THREADS, smem_bytes>>>(xs, xp, yp, out, total, n);
}